// round 13
// baseline (speedup 1.0000x reference)
#include <cuda_runtime.h>
#include <cuda_fp16.h>
#include <math.h>
#include <stdint.h>

#define MAX_N 100000
#define MAX_E 1600000
#define F 128
#define CHUNK 1024
#define NB ((MAX_N + CHUNK - 1) / CHUNK)
#define DEG_SCALE 33554432.0f    // 2^25 fixed-point for weighted degree

// ---------------- scratch (static device globals) ---------------------------
__device__ unsigned long long g_packed[MAX_N];      // hi: count, lo: deg fixed-point
__device__ float g_dinv[MAX_N];
__device__ __align__(16) __half g_xwh[MAX_N * F];   // x @ W1, fp16
__device__ float g_hw[MAX_N];
__device__ int   g_start[MAX_N + 1];
__device__ int   g_bsum[NB + 1];
__device__ __align__(16) int g_rank[MAX_E];         // within-target rank of each edge
__device__ __align__(16) int2 g_edge[MAX_E];        // {src_row, w=dinv[r]*ew as int}, CSR-sorted

// ---------------- edge pass: ONE packed atomic per edge (thread-per-edge) ----
__global__ void k_edge_pass(const int* __restrict__ col, const float* __restrict__ ew,
                            unsigned long long* packed, int* __restrict__ rank, int E) {
    int e = blockIdx.x * blockDim.x + threadIdx.x;
    if (e < E) {
        int c = col[e];
        unsigned int q = __float2uint_rn(ew[e] * DEG_SCALE);
        unsigned long long old =
            atomicAdd(&packed[c], (1ULL << 32) | (unsigned long long)q);
        rank[e] = (int)(old >> 32);
    }
}

// fused: dinv (with +1 self-loop) + per-chunk block sums of counts
__global__ void k_dinv_blocksum(const unsigned long long* __restrict__ packed,
                                float* __restrict__ dinv, int* bsum, int N) {
    __shared__ int s[256];
    int base = blockIdx.x * CHUNK;
    int t = threadIdx.x;
    int local = 0;
#pragma unroll
    for (int j = 0; j < 4; j++) {
        int i = base + t * 4 + j;
        if (i < N) {
            unsigned long long p = packed[i];
            local += (int)(p >> 32);
            float d = 1.0f + (float)(unsigned int)(p & 0xFFFFFFFFu) * (1.0f / DEG_SCALE);
            dinv[i] = rsqrtf(d);
        }
    }
    s[t] = local;
    __syncthreads();
    for (int off = 128; off > 0; off >>= 1) {
        if (t < off) s[t] += s[t + off];
        __syncthreads();
    }
    if (t == 0) bsum[blockIdx.x] = s[0];
}

// scan_scatter with INLINE bsum prefix
__global__ void k_scan_scatter(const unsigned long long* __restrict__ packed,
                               const int* __restrict__ bsum, int* start,
                               int nb, int N, int E) {
    __shared__ int s[256];
    __shared__ int sb[128];
    int base = blockIdx.x * CHUNK;
    int t = threadIdx.x;

    if (t < 128) sb[t] = (t < nb) ? bsum[t] : 0;
    __syncthreads();
    for (int off = 1; off < 128; off <<= 1) {
        int x = 0;
        if (t < 128 && t >= off) x = sb[t - off];
        __syncthreads();
        if (t < 128) sb[t] += x;
        __syncthreads();
    }
    int block_prefix = (blockIdx.x > 0) ? sb[blockIdx.x - 1] : 0;

    int v[4];
    int local = 0;
#pragma unroll
    for (int j = 0; j < 4; j++) {
        int i = base + t * 4 + j;
        v[j] = (i < N) ? (int)(packed[i] >> 32) : 0;
        local += v[j];
    }
    s[t] = local;
    __syncthreads();
    for (int off = 1; off < 256; off <<= 1) {
        int x = (t >= off) ? s[t - off] : 0;
        __syncthreads();
        s[t] += x;
        __syncthreads();
    }
    int excl = ((t > 0) ? s[t - 1] : 0) + block_prefix;
#pragma unroll
    for (int j = 0; j < 4; j++) {
        int i = base + t * 4 + j;
        if (i < N) {
            start[i] = excl;
            excl += v[j];
        }
    }
    if (blockIdx.x == 0 && t == 0) start[N] = E;
}

// ---------------- permute: 4 edges/thread; store {r, dinv[r]*ew} -------------
__global__ void k_permute(const int* __restrict__ row, const int* __restrict__ col,
                          const float* __restrict__ ew, const float* __restrict__ dinv,
                          const int* __restrict__ start, const int* __restrict__ rank,
                          int2* __restrict__ edge, int E) {
    int i = blockIdx.x * blockDim.x + threadIdx.x;
    int e = i * 4;
    if (e + 3 < E) {
        int4 r4 = __ldcs((const int4*)&row[e]);
        int4 c4 = __ldcs((const int4*)&col[e]);
        float4 w4 = __ldcs((const float4*)&ew[e]);
        int4 k4 = __ldcs((const int4*)&rank[e]);
        float wa = dinv[r4.x] * w4.x;
        float wb = dinv[r4.y] * w4.y;
        float wc = dinv[r4.z] * w4.z;
        float wd = dinv[r4.w] * w4.w;
        int pa = start[c4.x] + k4.x;
        int pb = start[c4.y] + k4.y;
        int pc = start[c4.z] + k4.z;
        int pd = start[c4.w] + k4.w;
        edge[pa] = make_int2(r4.x, __float_as_int(wa));
        edge[pb] = make_int2(r4.y, __float_as_int(wb));
        edge[pc] = make_int2(r4.z, __float_as_int(wc));
        edge[pd] = make_int2(r4.w, __float_as_int(wd));
    } else {
        for (; e < E; e++) {
            int r = row[e];
            int pos = start[col[e]] + rank[e];
            edge[pos] = make_int2(r, __float_as_int(dinv[r] * ew[e]));
        }
    }
}

// ---------------- fp16 tensor-core GEMM: Y(fp16) = X @ W1 --------------------
__global__ void __launch_bounds__(256, 2)
k_gemm_f16(const float* __restrict__ X, const float* __restrict__ W1,
           __half* __restrict__ Y, int N) {
    __shared__ __half  Xs[2][128][24];
    __shared__ uint32_t Ws[2][8][136];

    int tid  = threadIdx.x;
    int lane = tid & 31;
    int wid  = tid >> 5;
    int wr   = wid >> 1;
    int wc   = wid & 1;
    int g    = lane >> 2;
    int tig  = lane & 3;
    int row0 = blockIdx.x * 128;

    int xr0 = tid >> 2,           xk0 = (tid & 3) * 4;
    int xr1 = (tid + 256) >> 2,   xk1 = (tid & 3) * 4;
    int wcc = tid & 127;
    int wkp = (tid >> 7) * 4;

    float acc[2][8][4];
#pragma unroll
    for (int rt = 0; rt < 2; rt++)
#pragma unroll
        for (int nt = 0; nt < 8; nt++)
#pragma unroll
            for (int j = 0; j < 4; j++) acc[rt][nt][j] = 0.0f;

    float4 xv0, xv1;
    float wa[4], wb[4];

    auto fetch = [&](int c) {
        int k0 = c * 16;
        int gr0 = row0 + xr0, gr1 = row0 + xr1;
        xv0 = (gr0 < N) ? __ldcs((const float4*)&X[(long)gr0 * F + k0 + xk0]) : make_float4(0,0,0,0);
        xv1 = (gr1 < N) ? __ldcs((const float4*)&X[(long)gr1 * F + k0 + xk1]) : make_float4(0,0,0,0);
#pragma unroll
        for (int j = 0; j < 4; j++) {
            int kk = k0 + 2 * (wkp + j);
            wa[j] = W1[kk * F + wcc];
            wb[j] = W1[(kk + 1) * F + wcc];
        }
    };
    auto stage = [&](int b) {
        __half2* px0 = (__half2*)&Xs[b][xr0][xk0];
        px0[0] = __floats2half2_rn(xv0.x, xv0.y);
        px0[1] = __floats2half2_rn(xv0.z, xv0.w);
        __half2* px1 = (__half2*)&Xs[b][xr1][xk1];
        px1[0] = __floats2half2_rn(xv1.x, xv1.y);
        px1[1] = __floats2half2_rn(xv1.z, xv1.w);
#pragma unroll
        for (int j = 0; j < 4; j++) {
            __half2 h = __floats2half2_rn(wa[j], wb[j]);
            Ws[b][wkp + j][wcc] = *(uint32_t*)&h;
        }
    };

    fetch(0);
    stage(0);
    __syncthreads();

    int p = 0;
#pragma unroll
    for (int c = 0; c < 8; c++) {
        if (c < 7) fetch(c + 1);

        uint32_t bf[8][2];
#pragma unroll
        for (int nt = 0; nt < 8; nt++) {
            int cc = wc * 64 + nt * 8 + g;
            bf[nt][0] = Ws[p][tig][cc];
            bf[nt][1] = Ws[p][tig + 4][cc];
        }

#pragma unroll
        for (int rt = 0; rt < 2; rt++) {
            int rb = wr * 32 + rt * 16;
            uint32_t a0 = *(const uint32_t*)&Xs[p][rb + g][2 * tig];
            uint32_t a1 = *(const uint32_t*)&Xs[p][rb + g + 8][2 * tig];
            uint32_t a2 = *(const uint32_t*)&Xs[p][rb + g][2 * tig + 8];
            uint32_t a3 = *(const uint32_t*)&Xs[p][rb + g + 8][2 * tig + 8];
#pragma unroll
            for (int nt = 0; nt < 8; nt++) {
                float* d = acc[rt][nt];
                asm volatile(
                    "mma.sync.aligned.m16n8k16.row.col.f32.f16.f16.f32 "
                    "{%0,%1,%2,%3}, {%4,%5,%6,%7}, {%8,%9}, {%0,%1,%2,%3};"
                    : "+f"(d[0]), "+f"(d[1]), "+f"(d[2]), "+f"(d[3])
                    : "r"(a0), "r"(a1), "r"(a2), "r"(a3),
                      "r"(bf[nt][0]), "r"(bf[nt][1]));
            }
        }

        if (c < 7) {
            stage(1 - p);
            __syncthreads();
            p ^= 1;
        }
    }

#pragma unroll
    for (int rt = 0; rt < 2; rt++) {
        int r0g = row0 + wr * 32 + rt * 16 + g;
        int r1g = r0g + 8;
#pragma unroll
        for (int nt = 0; nt < 8; nt++) {
            int cc = wc * 64 + nt * 8 + 2 * tig;
            if (r0g < N)
                *(__half2*)&Y[(long)r0g * F + cc] = __floats2half2_rn(acc[rt][nt][0], acc[rt][nt][1]);
            if (r1g < N)
                *(__half2*)&Y[(long)r1g * F + cc] = __floats2half2_rn(acc[rt][nt][2], acc[rt][nt][3]);
        }
    }
}

// ---------------- layer 1 gather (CSR, fp16 messages) + fused h@W2 ----------
__device__ __forceinline__ void acc_row(float4& acc, const __half* base, int lane, float n) {
    uint2 u = ((const uint2*)base)[lane];
    float2 f01 = __half22float2(*reinterpret_cast<__half2*>(&u.x));
    float2 f23 = __half22float2(*reinterpret_cast<__half2*>(&u.y));
    acc.x += n * f01.x; acc.y += n * f01.y;
    acc.z += n * f23.x; acc.w += n * f23.y;
}

__global__ void k_gather1(const int* __restrict__ start, const int2* __restrict__ edge,
                          const __half* __restrict__ xwh,
                          const float* __restrict__ dinv, const float* __restrict__ b1,
                          const float* __restrict__ W2,
                          float* __restrict__ emb, float* __restrict__ hw, int N) {
    int node = blockIdx.x * (blockDim.x >> 5) + (threadIdx.x >> 5);
    if (node >= N) return;
    int lane = threadIdx.x & 31;

    // hoisted independent loads (overlap with the gather chain)
    float dc = dinv[node];
    float4 b  = ((const float4*)b1)[lane];
    float4 wv = ((const float4*)W2)[lane];

    float4 acc = make_float4(0.f, 0.f, 0.f, 0.f);

    int e  = start[node];
    int e1 = start[node + 1];
    for (; e + 3 < e1; e += 4) {
        int2 p0 = edge[e],   p1 = edge[e+1], p2 = edge[e+2], p3 = edge[e+3];
        acc_row(acc, &xwh[(long)p0.x * F], lane, __int_as_float(p0.y));
        acc_row(acc, &xwh[(long)p1.x * F], lane, __int_as_float(p1.y));
        acc_row(acc, &xwh[(long)p2.x * F], lane, __int_as_float(p2.y));
        acc_row(acc, &xwh[(long)p3.x * F], lane, __int_as_float(p3.y));
    }
    for (; e < e1; e++) {
        int2 p0 = edge[e];
        acc_row(acc, &xwh[(long)p0.x * F], lane, __int_as_float(p0.y));
    }

    // self-loop (weight dinv_c), then scale whole sum by dinv_c
    acc_row(acc, &xwh[(long)node * F], lane, dc);
    acc.x *= dc; acc.y *= dc; acc.z *= dc; acc.w *= dc;

    acc.x += b.x; acc.y += b.y; acc.z += b.z; acc.w += b.w;
    acc.x = (acc.x > 0.f) ? acc.x : expm1f(acc.x);
    acc.y = (acc.y > 0.f) ? acc.y : expm1f(acc.y);
    acc.z = (acc.z > 0.f) ? acc.z : expm1f(acc.z);
    acc.w = (acc.w > 0.f) ? acc.w : expm1f(acc.w);
    __stwt((float4*)&emb[(long)node * F + lane * 4], acc);

    float d = acc.x * wv.x + acc.y * wv.y + acc.z * wv.z + acc.w * wv.w;
#pragma unroll
    for (int o = 16; o > 0; o >>= 1) d += __shfl_xor_sync(0xFFFFFFFFu, d, o);
    if (lane == 0) hw[node] = d;
}

// ---------------- layer 2: thread per node, 4-edge unroll --------------------
__global__ void k_gather2(const int* __restrict__ start, const int2* __restrict__ edge,
                          const float* __restrict__ hw,
                          const float* __restrict__ dinv, const float* __restrict__ b2,
                          float* __restrict__ out, int N) {
    int node = blockIdx.x * blockDim.x + threadIdx.x;
    if (node >= N) return;
    float dc = dinv[node];
    float sum = 0.0f;
    int e  = start[node];
    int e1 = start[node + 1];
    for (; e + 3 < e1; e += 4) {
        int2 p0 = edge[e],     p1 = edge[e + 1];
        int2 p2 = edge[e + 2], p3 = edge[e + 3];
        sum += __int_as_float(p0.y) * hw[p0.x] + __int_as_float(p1.y) * hw[p1.x]
             + __int_as_float(p2.y) * hw[p2.x] + __int_as_float(p3.y) * hw[p3.x];
    }
    for (; e < e1; e++) {
        int2 p0 = edge[e];
        sum += __int_as_float(p0.y) * hw[p0.x];
    }
    float v = dc * (sum + dc * hw[node]) + b2[0];
    out[node] = 1.0f / (1.0f + expf(-v));
}

// ---------------- launch ------------------------------------------------------
extern "C" void kernel_launch(void* const* d_in, const int* in_sizes, int n_in,
                              void* d_out, int out_size) {
    const float* x   = (const float*)d_in[0];
    const int*   ei  = (const int*)d_in[1];
    const float* ew  = (const float*)d_in[2];
    const float* W1  = (const float*)d_in[3];
    const float* b1  = (const float*)d_in[4];
    const float* W2  = (const float*)d_in[5];
    const float* b2  = (const float*)d_in[6];

    int N = in_sizes[0] / F;
    int E = in_sizes[2];
    const int* row = ei;
    const int* col = ei + E;

    float* out_pred = (float*)d_out;
    float* emb      = (float*)d_out + N;

    unsigned long long* packed = nullptr; cudaGetSymbolAddress((void**)&packed, g_packed);
    float*  dinv  = nullptr; cudaGetSymbolAddress((void**)&dinv,  g_dinv);
    __half* xwh   = nullptr; cudaGetSymbolAddress((void**)&xwh,   g_xwh);
    float*  hw    = nullptr; cudaGetSymbolAddress((void**)&hw,    g_hw);
    int*    start = nullptr; cudaGetSymbolAddress((void**)&start, g_start);
    int*    bsum  = nullptr; cudaGetSymbolAddress((void**)&bsum,  g_bsum);
    int*    rank  = nullptr; cudaGetSymbolAddress((void**)&rank,  g_rank);
    int2*   edge  = nullptr; cudaGetSymbolAddress((void**)&edge,  g_edge);

    int nb = (N + CHUNK - 1) / CHUNK;

    static cudaStream_t s2 = nullptr;
    static cudaEvent_t ev_fork = nullptr, ev_join = nullptr;
    if (s2 == nullptr) {
        cudaStreamCreateWithFlags(&s2, cudaStreamNonBlocking);
        cudaEventCreateWithFlags(&ev_fork, cudaEventDisableTiming);
        cudaEventCreateWithFlags(&ev_join, cudaEventDisableTiming);
    }

    cudaEventRecord(ev_fork, 0);
    cudaStreamWaitEvent(s2, ev_fork, 0);

    // main stream: fp16 tensor-core GEMM
    k_gemm_f16<<<(N + 127) / 128, 256>>>(x, W1, xwh, N);

    // s2: CSR build
    cudaMemsetAsync(packed, 0, (size_t)N * sizeof(unsigned long long), s2);
    k_edge_pass<<<(E + 255) / 256, 256, 0, s2>>>(col, ew, packed, rank, E);
    k_dinv_blocksum<<<nb, 256, 0, s2>>>(packed, dinv, bsum, N);
    k_scan_scatter<<<nb, 256, 0, s2>>>(packed, bsum, start, nb, N, E);
    k_permute<<<((E + 3) / 4 + 255) / 256, 256, 0, s2>>>(row, col, ew, dinv, start, rank, edge, E);

    cudaEventRecord(ev_join, s2);
    cudaStreamWaitEvent(0, ev_join, 0);

    k_gather1<<<(N + 7) / 8, 256>>>(start, edge, xwh, dinv, b1, W2, emb, hw, N);
    k_gather2<<<(N + 255) / 256, 256>>>(start, edge, hw, dinv, b2, out_pred, N);
}

// round 14
// speedup vs baseline: 1.0908x; 1.0908x over previous
#include <cuda_runtime.h>
#include <cuda_fp16.h>
#include <math.h>
#include <stdint.h>

#define MAX_N 100000
#define MAX_E 1600000
#define F 128
#define CHUNK 1024
#define NB ((MAX_N + CHUNK - 1) / CHUNK)
#define DEG_SCALE 33554432.0f    // 2^25 fixed-point for weighted degree

// ---------------- scratch (static device globals) ---------------------------
__device__ unsigned long long g_packed[MAX_N];      // hi: count, lo: deg fixed-point
__device__ float g_dinv[MAX_N];
__device__ __align__(16) __half g_xwh[MAX_N * F];   // x @ W1, fp16
__device__ float g_hw[MAX_N];
__device__ int   g_start[MAX_N + 1];
__device__ int   g_bsum[NB + 1];
__device__ __align__(16) int g_rank[MAX_E];         // within-target rank of each edge
__device__ __align__(16) int2 g_edge[MAX_E];        // {src_row, w=dinv[r]*ew as int}, CSR-sorted

// ---------------- edge pass: ONE packed atomic per edge (thread-per-edge) ----
__global__ void k_edge_pass(const int* __restrict__ col, const float* __restrict__ ew,
                            unsigned long long* packed, int* __restrict__ rank, int E) {
    int e = blockIdx.x * blockDim.x + threadIdx.x;
    if (e < E) {
        int c = col[e];
        unsigned int q = __float2uint_rn(ew[e] * DEG_SCALE);
        unsigned long long old =
            atomicAdd(&packed[c], (1ULL << 32) | (unsigned long long)q);
        rank[e] = (int)(old >> 32);
    }
}

// fused: dinv (with +1 self-loop) + per-chunk block sums of counts
__global__ void k_dinv_blocksum(const unsigned long long* __restrict__ packed,
                                float* __restrict__ dinv, int* bsum, int N) {
    __shared__ int s[256];
    int base = blockIdx.x * CHUNK;
    int t = threadIdx.x;
    int local = 0;
#pragma unroll
    for (int j = 0; j < 4; j++) {
        int i = base + t * 4 + j;
        if (i < N) {
            unsigned long long p = packed[i];
            local += (int)(p >> 32);
            float d = 1.0f + (float)(unsigned int)(p & 0xFFFFFFFFu) * (1.0f / DEG_SCALE);
            dinv[i] = rsqrtf(d);
        }
    }
    s[t] = local;
    __syncthreads();
    for (int off = 128; off > 0; off >>= 1) {
        if (t < off) s[t] += s[t + off];
        __syncthreads();
    }
    if (t == 0) bsum[blockIdx.x] = s[0];
}

// scan_scatter with INLINE bsum prefix
__global__ void k_scan_scatter(const unsigned long long* __restrict__ packed,
                               const int* __restrict__ bsum, int* start,
                               int nb, int N, int E) {
    __shared__ int s[256];
    __shared__ int sb[128];
    int base = blockIdx.x * CHUNK;
    int t = threadIdx.x;

    if (t < 128) sb[t] = (t < nb) ? bsum[t] : 0;
    __syncthreads();
    for (int off = 1; off < 128; off <<= 1) {
        int x = 0;
        if (t < 128 && t >= off) x = sb[t - off];
        __syncthreads();
        if (t < 128) sb[t] += x;
        __syncthreads();
    }
    int block_prefix = (blockIdx.x > 0) ? sb[blockIdx.x - 1] : 0;

    int v[4];
    int local = 0;
#pragma unroll
    for (int j = 0; j < 4; j++) {
        int i = base + t * 4 + j;
        v[j] = (i < N) ? (int)(packed[i] >> 32) : 0;
        local += v[j];
    }
    s[t] = local;
    __syncthreads();
    for (int off = 1; off < 256; off <<= 1) {
        int x = (t >= off) ? s[t - off] : 0;
        __syncthreads();
        s[t] += x;
        __syncthreads();
    }
    int excl = ((t > 0) ? s[t - 1] : 0) + block_prefix;
#pragma unroll
    for (int j = 0; j < 4; j++) {
        int i = base + t * 4 + j;
        if (i < N) {
            start[i] = excl;
            excl += v[j];
        }
    }
    if (blockIdx.x == 0 && t == 0) start[N] = E;
}

// ---------------- permute: 4 edges/thread; store {r, dinv[r]*ew} -------------
__global__ void k_permute(const int* __restrict__ row, const int* __restrict__ col,
                          const float* __restrict__ ew, const float* __restrict__ dinv,
                          const int* __restrict__ start, const int* __restrict__ rank,
                          int2* __restrict__ edge, int E) {
    int i = blockIdx.x * blockDim.x + threadIdx.x;
    int e = i * 4;
    if (e + 3 < E) {
        int4 r4 = *(const int4*)&row[e];
        int4 c4 = *(const int4*)&col[e];
        float4 w4 = *(const float4*)&ew[e];
        int4 k4 = *(const int4*)&rank[e];
        float wa = dinv[r4.x] * w4.x;
        float wb = dinv[r4.y] * w4.y;
        float wc = dinv[r4.z] * w4.z;
        float wd = dinv[r4.w] * w4.w;
        int pa = start[c4.x] + k4.x;
        int pb = start[c4.y] + k4.y;
        int pc = start[c4.z] + k4.z;
        int pd = start[c4.w] + k4.w;
        edge[pa] = make_int2(r4.x, __float_as_int(wa));
        edge[pb] = make_int2(r4.y, __float_as_int(wb));
        edge[pc] = make_int2(r4.z, __float_as_int(wc));
        edge[pd] = make_int2(r4.w, __float_as_int(wd));
    } else {
        for (; e < E; e++) {
            int r = row[e];
            int pos = start[col[e]] + rank[e];
            edge[pos] = make_int2(r, __float_as_int(dinv[r] * ew[e]));
        }
    }
}

// ---------------- fp16 tensor-core GEMM: Y(fp16) = X @ W1 --------------------
__global__ void __launch_bounds__(256, 2)
k_gemm_f16(const float* __restrict__ X, const float* __restrict__ W1,
           __half* __restrict__ Y, int N) {
    __shared__ __half  Xs[2][128][24];
    __shared__ uint32_t Ws[2][8][136];

    int tid  = threadIdx.x;
    int lane = tid & 31;
    int wid  = tid >> 5;
    int wr   = wid >> 1;
    int wc   = wid & 1;
    int g    = lane >> 2;
    int tig  = lane & 3;
    int row0 = blockIdx.x * 128;

    int xr0 = tid >> 2,           xk0 = (tid & 3) * 4;
    int xr1 = (tid + 256) >> 2,   xk1 = (tid & 3) * 4;
    int wcc = tid & 127;
    int wkp = (tid >> 7) * 4;

    float acc[2][8][4];
#pragma unroll
    for (int rt = 0; rt < 2; rt++)
#pragma unroll
        for (int nt = 0; nt < 8; nt++)
#pragma unroll
            for (int j = 0; j < 4; j++) acc[rt][nt][j] = 0.0f;

    float4 xv0, xv1;
    float wa[4], wb[4];

    auto fetch = [&](int c) {
        int k0 = c * 16;
        int gr0 = row0 + xr0, gr1 = row0 + xr1;
        xv0 = (gr0 < N) ? __ldcs((const float4*)&X[(long)gr0 * F + k0 + xk0]) : make_float4(0,0,0,0);
        xv1 = (gr1 < N) ? __ldcs((const float4*)&X[(long)gr1 * F + k0 + xk1]) : make_float4(0,0,0,0);
#pragma unroll
        for (int j = 0; j < 4; j++) {
            int kk = k0 + 2 * (wkp + j);
            wa[j] = W1[kk * F + wcc];
            wb[j] = W1[(kk + 1) * F + wcc];
        }
    };
    auto stage = [&](int b) {
        __half2* px0 = (__half2*)&Xs[b][xr0][xk0];
        px0[0] = __floats2half2_rn(xv0.x, xv0.y);
        px0[1] = __floats2half2_rn(xv0.z, xv0.w);
        __half2* px1 = (__half2*)&Xs[b][xr1][xk1];
        px1[0] = __floats2half2_rn(xv1.x, xv1.y);
        px1[1] = __floats2half2_rn(xv1.z, xv1.w);
#pragma unroll
        for (int j = 0; j < 4; j++) {
            __half2 h = __floats2half2_rn(wa[j], wb[j]);
            Ws[b][wkp + j][wcc] = *(uint32_t*)&h;
        }
    };

    fetch(0);
    stage(0);
    __syncthreads();

    int p = 0;
#pragma unroll
    for (int c = 0; c < 8; c++) {
        if (c < 7) fetch(c + 1);

        uint32_t bf[8][2];
#pragma unroll
        for (int nt = 0; nt < 8; nt++) {
            int cc = wc * 64 + nt * 8 + g;
            bf[nt][0] = Ws[p][tig][cc];
            bf[nt][1] = Ws[p][tig + 4][cc];
        }

#pragma unroll
        for (int rt = 0; rt < 2; rt++) {
            int rb = wr * 32 + rt * 16;
            uint32_t a0 = *(const uint32_t*)&Xs[p][rb + g][2 * tig];
            uint32_t a1 = *(const uint32_t*)&Xs[p][rb + g + 8][2 * tig];
            uint32_t a2 = *(const uint32_t*)&Xs[p][rb + g][2 * tig + 8];
            uint32_t a3 = *(const uint32_t*)&Xs[p][rb + g + 8][2 * tig + 8];
#pragma unroll
            for (int nt = 0; nt < 8; nt++) {
                float* d = acc[rt][nt];
                asm volatile(
                    "mma.sync.aligned.m16n8k16.row.col.f32.f16.f16.f32 "
                    "{%0,%1,%2,%3}, {%4,%5,%6,%7}, {%8,%9}, {%0,%1,%2,%3};"
                    : "+f"(d[0]), "+f"(d[1]), "+f"(d[2]), "+f"(d[3])
                    : "r"(a0), "r"(a1), "r"(a2), "r"(a3),
                      "r"(bf[nt][0]), "r"(bf[nt][1]));
            }
        }

        if (c < 7) {
            stage(1 - p);
            __syncthreads();
            p ^= 1;
        }
    }

#pragma unroll
    for (int rt = 0; rt < 2; rt++) {
        int r0g = row0 + wr * 32 + rt * 16 + g;
        int r1g = r0g + 8;
#pragma unroll
        for (int nt = 0; nt < 8; nt++) {
            int cc = wc * 64 + nt * 8 + 2 * tig;
            if (r0g < N)
                *(__half2*)&Y[(long)r0g * F + cc] = __floats2half2_rn(acc[rt][nt][0], acc[rt][nt][1]);
            if (r1g < N)
                *(__half2*)&Y[(long)r1g * F + cc] = __floats2half2_rn(acc[rt][nt][2], acc[rt][nt][3]);
        }
    }
}

// ---------------- layer 1 gather (CSR, fp16 messages) + fused h@W2 ----------
__device__ __forceinline__ void acc_row(float4& acc, const __half* base, int lane, float n) {
    uint2 u = ((const uint2*)base)[lane];
    float2 f01 = __half22float2(*reinterpret_cast<__half2*>(&u.x));
    float2 f23 = __half22float2(*reinterpret_cast<__half2*>(&u.y));
    acc.x += n * f01.x; acc.y += n * f01.y;
    acc.z += n * f23.x; acc.w += n * f23.y;
}

__global__ void k_gather1(const int* __restrict__ start, const int2* __restrict__ edge,
                          const __half* __restrict__ xwh,
                          const float* __restrict__ dinv, const float* __restrict__ b1,
                          const float* __restrict__ W2,
                          float* __restrict__ emb, float* __restrict__ hw, int N) {
    int node = blockIdx.x * (blockDim.x >> 5) + (threadIdx.x >> 5);
    if (node >= N) return;
    int lane = threadIdx.x & 31;

    float dc = dinv[node];
    float4 acc = make_float4(0.f, 0.f, 0.f, 0.f);

    int e  = start[node];
    int e1 = start[node + 1];
    for (; e + 3 < e1; e += 4) {
        int2 p0 = edge[e],   p1 = edge[e+1], p2 = edge[e+2], p3 = edge[e+3];
        acc_row(acc, &xwh[(long)p0.x * F], lane, __int_as_float(p0.y));
        acc_row(acc, &xwh[(long)p1.x * F], lane, __int_as_float(p1.y));
        acc_row(acc, &xwh[(long)p2.x * F], lane, __int_as_float(p2.y));
        acc_row(acc, &xwh[(long)p3.x * F], lane, __int_as_float(p3.y));
    }
    for (; e < e1; e++) {
        int2 p0 = edge[e];
        acc_row(acc, &xwh[(long)p0.x * F], lane, __int_as_float(p0.y));
    }

    // self-loop (weight dinv_c), then scale whole sum by dinv_c
    acc_row(acc, &xwh[(long)node * F], lane, dc);
    acc.x *= dc; acc.y *= dc; acc.z *= dc; acc.w *= dc;

    float4 b = ((const float4*)b1)[lane];
    acc.x += b.x; acc.y += b.y; acc.z += b.z; acc.w += b.w;
    acc.x = (acc.x > 0.f) ? acc.x : expm1f(acc.x);
    acc.y = (acc.y > 0.f) ? acc.y : expm1f(acc.y);
    acc.z = (acc.z > 0.f) ? acc.z : expm1f(acc.z);
    acc.w = (acc.w > 0.f) ? acc.w : expm1f(acc.w);
    __stwt((float4*)&emb[(long)node * F + lane * 4], acc);

    float4 wv = ((const float4*)W2)[lane];
    float d = acc.x * wv.x + acc.y * wv.y + acc.z * wv.z + acc.w * wv.w;
#pragma unroll
    for (int o = 16; o > 0; o >>= 1) d += __shfl_xor_sync(0xFFFFFFFFu, d, o);
    if (lane == 0) hw[node] = d;
}

// ---------------- layer 2: thread per node, 4-edge unroll --------------------
__global__ void k_gather2(const int* __restrict__ start, const int2* __restrict__ edge,
                          const float* __restrict__ hw,
                          const float* __restrict__ dinv, const float* __restrict__ b2,
                          float* __restrict__ out, int N) {
    int node = blockIdx.x * blockDim.x + threadIdx.x;
    if (node >= N) return;
    float dc = dinv[node];
    float sum = 0.0f;
    int e  = start[node];
    int e1 = start[node + 1];
    for (; e + 3 < e1; e += 4) {
        int2 p0 = edge[e],     p1 = edge[e + 1];
        int2 p2 = edge[e + 2], p3 = edge[e + 3];
        sum += __int_as_float(p0.y) * hw[p0.x] + __int_as_float(p1.y) * hw[p1.x]
             + __int_as_float(p2.y) * hw[p2.x] + __int_as_float(p3.y) * hw[p3.x];
    }
    for (; e < e1; e++) {
        int2 p0 = edge[e];
        sum += __int_as_float(p0.y) * hw[p0.x];
    }
    float v = dc * (sum + dc * hw[node]) + b2[0];
    out[node] = 1.0f / (1.0f + expf(-v));
}

// ---------------- launch ------------------------------------------------------
extern "C" void kernel_launch(void* const* d_in, const int* in_sizes, int n_in,
                              void* d_out, int out_size) {
    const float* x   = (const float*)d_in[0];
    const int*   ei  = (const int*)d_in[1];
    const float* ew  = (const float*)d_in[2];
    const float* W1  = (const float*)d_in[3];
    const float* b1  = (const float*)d_in[4];
    const float* W2  = (const float*)d_in[5];
    const float* b2  = (const float*)d_in[6];

    int N = in_sizes[0] / F;
    int E = in_sizes[2];
    const int* row = ei;
    const int* col = ei + E;

    float* out_pred = (float*)d_out;
    float* emb      = (float*)d_out + N;

    unsigned long long* packed = nullptr; cudaGetSymbolAddress((void**)&packed, g_packed);
    float*  dinv  = nullptr; cudaGetSymbolAddress((void**)&dinv,  g_dinv);
    __half* xwh   = nullptr; cudaGetSymbolAddress((void**)&xwh,   g_xwh);
    float*  hw    = nullptr; cudaGetSymbolAddress((void**)&hw,    g_hw);
    int*    start = nullptr; cudaGetSymbolAddress((void**)&start, g_start);
    int*    bsum  = nullptr; cudaGetSymbolAddress((void**)&bsum,  g_bsum);
    int*    rank  = nullptr; cudaGetSymbolAddress((void**)&rank,  g_rank);
    int2*   edge  = nullptr; cudaGetSymbolAddress((void**)&edge,  g_edge);

    int nb = (N + CHUNK - 1) / CHUNK;

    static cudaStream_t s2 = nullptr;
    static cudaEvent_t ev_fork = nullptr, ev_join = nullptr;
    if (s2 == nullptr) {
        cudaStreamCreateWithFlags(&s2, cudaStreamNonBlocking);
        cudaEventCreateWithFlags(&ev_fork, cudaEventDisableTiming);
        cudaEventCreateWithFlags(&ev_join, cudaEventDisableTiming);
    }

    cudaEventRecord(ev_fork, 0);
    cudaStreamWaitEvent(s2, ev_fork, 0);

    // main stream: fp16 tensor-core GEMM
    k_gemm_f16<<<(N + 127) / 128, 256>>>(x, W1, xwh, N);

    // s2: CSR build
    cudaMemsetAsync(packed, 0, (size_t)N * sizeof(unsigned long long), s2);
    k_edge_pass<<<(E + 255) / 256, 256, 0, s2>>>(col, ew, packed, rank, E);
    k_dinv_blocksum<<<nb, 256, 0, s2>>>(packed, dinv, bsum, N);
    k_scan_scatter<<<nb, 256, 0, s2>>>(packed, bsum, start, nb, N, E);
    k_permute<<<((E + 3) / 4 + 255) / 256, 256, 0, s2>>>(row, col, ew, dinv, start, rank, edge, E);

    cudaEventRecord(ev_join, s2);
    cudaStreamWaitEvent(0, ev_join, 0);

    k_gather1<<<(N + 7) / 8, 256>>>(start, edge, xwh, dinv, b1, W2, emb, hw, N);
    k_gather2<<<(N + 255) / 256, 256>>>(start, edge, hw, dinv, b2, out_pred, N);
}

// round 15
// speedup vs baseline: 1.1227x; 1.0292x over previous
#include <cuda_runtime.h>
#include <cuda_fp16.h>
#include <math.h>
#include <stdint.h>

#define MAX_N 100000
#define MAX_E 1600000
#define F 128
#define CHUNK 1024
#define NB ((MAX_N + CHUNK - 1) / CHUNK)
#define DEG_SCALE 33554432.0f    // 2^25 fixed-point for weighted degree

// ---------------- scratch (static device globals) ---------------------------
__device__ unsigned long long g_packed[MAX_N];      // hi: count, lo: deg fixed-point
__device__ float g_dinv[MAX_N];
__device__ __align__(16) __half g_xwh[MAX_N * F];   // x @ W1, fp16
__device__ float g_hw[MAX_N];
__device__ int   g_start[MAX_N + 1];
__device__ int   g_bsum[NB + 1];
__device__ __align__(16) int g_rank[MAX_E];         // within-target rank of each edge
__device__ __align__(16) unsigned int g_edge[MAX_E]; // packed {r:17 | half(w):15}, CSR-sorted

// ---------------- edge packing helpers ---------------------------------------
__device__ __forceinline__ unsigned int pack_edge(int r, float w) {
    unsigned short hb = __half_as_ushort(__float2half(w));
    return ((unsigned int)r << 15) | (hb & 0x7FFFu);
}
__device__ __forceinline__ int edge_row(unsigned int u) { return (int)(u >> 15); }
__device__ __forceinline__ float edge_w(unsigned int u) {
    return __half2float(__ushort_as_half((unsigned short)(u & 0x7FFFu)));
}

// ---------------- edge pass: ONE packed atomic per edge (thread-per-edge) ----
__global__ void k_edge_pass(const int* __restrict__ col, const float* __restrict__ ew,
                            unsigned long long* packed, int* __restrict__ rank, int E) {
    int e = blockIdx.x * blockDim.x + threadIdx.x;
    if (e < E) {
        int c = col[e];
        unsigned int q = __float2uint_rn(ew[e] * DEG_SCALE);
        unsigned long long old =
            atomicAdd(&packed[c], (1ULL << 32) | (unsigned long long)q);
        rank[e] = (int)(old >> 32);
    }
}

// fused: dinv (with +1 self-loop) + per-chunk block sums of counts
__global__ void k_dinv_blocksum(const unsigned long long* __restrict__ packed,
                                float* __restrict__ dinv, int* bsum, int N) {
    __shared__ int s[256];
    int base = blockIdx.x * CHUNK;
    int t = threadIdx.x;
    int local = 0;
#pragma unroll
    for (int j = 0; j < 4; j++) {
        int i = base + t * 4 + j;
        if (i < N) {
            unsigned long long p = packed[i];
            local += (int)(p >> 32);
            float d = 1.0f + (float)(unsigned int)(p & 0xFFFFFFFFu) * (1.0f / DEG_SCALE);
            dinv[i] = rsqrtf(d);
        }
    }
    s[t] = local;
    __syncthreads();
    for (int off = 128; off > 0; off >>= 1) {
        if (t < off) s[t] += s[t + off];
        __syncthreads();
    }
    if (t == 0) bsum[blockIdx.x] = s[0];
}

// scan_scatter with INLINE bsum prefix
__global__ void k_scan_scatter(const unsigned long long* __restrict__ packed,
                               const int* __restrict__ bsum, int* start,
                               int nb, int N, int E) {
    __shared__ int s[256];
    __shared__ int sb[128];
    int base = blockIdx.x * CHUNK;
    int t = threadIdx.x;

    if (t < 128) sb[t] = (t < nb) ? bsum[t] : 0;
    __syncthreads();
    for (int off = 1; off < 128; off <<= 1) {
        int x = 0;
        if (t < 128 && t >= off) x = sb[t - off];
        __syncthreads();
        if (t < 128) sb[t] += x;
        __syncthreads();
    }
    int block_prefix = (blockIdx.x > 0) ? sb[blockIdx.x - 1] : 0;

    int v[4];
    int local = 0;
#pragma unroll
    for (int j = 0; j < 4; j++) {
        int i = base + t * 4 + j;
        v[j] = (i < N) ? (int)(packed[i] >> 32) : 0;
        local += v[j];
    }
    s[t] = local;
    __syncthreads();
    for (int off = 1; off < 256; off <<= 1) {
        int x = (t >= off) ? s[t - off] : 0;
        __syncthreads();
        s[t] += x;
        __syncthreads();
    }
    int excl = ((t > 0) ? s[t - 1] : 0) + block_prefix;
#pragma unroll
    for (int j = 0; j < 4; j++) {
        int i = base + t * 4 + j;
        if (i < N) {
            start[i] = excl;
            excl += v[j];
        }
    }
    if (blockIdx.x == 0 && t == 0) start[N] = E;
}

// ---------------- permute: 4 edges/thread; store packed {r, half(dinv[r]*ew)} -
__global__ void k_permute(const int* __restrict__ row, const int* __restrict__ col,
                          const float* __restrict__ ew, const float* __restrict__ dinv,
                          const int* __restrict__ start, const int* __restrict__ rank,
                          unsigned int* __restrict__ edge, int E) {
    int i = blockIdx.x * blockDim.x + threadIdx.x;
    int e = i * 4;
    if (e + 3 < E) {
        int4 r4 = *(const int4*)&row[e];
        int4 c4 = *(const int4*)&col[e];
        float4 w4 = *(const float4*)&ew[e];
        int4 k4 = *(const int4*)&rank[e];
        float wa = dinv[r4.x] * w4.x;
        float wb = dinv[r4.y] * w4.y;
        float wc = dinv[r4.z] * w4.z;
        float wd = dinv[r4.w] * w4.w;
        int pa = start[c4.x] + k4.x;
        int pb = start[c4.y] + k4.y;
        int pc = start[c4.z] + k4.z;
        int pd = start[c4.w] + k4.w;
        edge[pa] = pack_edge(r4.x, wa);
        edge[pb] = pack_edge(r4.y, wb);
        edge[pc] = pack_edge(r4.z, wc);
        edge[pd] = pack_edge(r4.w, wd);
    } else {
        for (; e < E; e++) {
            int r = row[e];
            int pos = start[col[e]] + rank[e];
            edge[pos] = pack_edge(r, dinv[r] * ew[e]);
        }
    }
}

// ---------------- fp16 tensor-core GEMM: Y(fp16) = X @ W1 --------------------
__global__ void __launch_bounds__(256, 2)
k_gemm_f16(const float* __restrict__ X, const float* __restrict__ W1,
           __half* __restrict__ Y, int N) {
    __shared__ __half  Xs[2][128][24];
    __shared__ uint32_t Ws[2][8][136];

    int tid  = threadIdx.x;
    int lane = tid & 31;
    int wid  = tid >> 5;
    int wr   = wid >> 1;
    int wc   = wid & 1;
    int g    = lane >> 2;
    int tig  = lane & 3;
    int row0 = blockIdx.x * 128;

    int xr0 = tid >> 2,           xk0 = (tid & 3) * 4;
    int xr1 = (tid + 256) >> 2,   xk1 = (tid & 3) * 4;
    int wcc = tid & 127;
    int wkp = (tid >> 7) * 4;

    float acc[2][8][4];
#pragma unroll
    for (int rt = 0; rt < 2; rt++)
#pragma unroll
        for (int nt = 0; nt < 8; nt++)
#pragma unroll
            for (int j = 0; j < 4; j++) acc[rt][nt][j] = 0.0f;

    float4 xv0, xv1;
    float wa[4], wb[4];

    auto fetch = [&](int c) {
        int k0 = c * 16;
        int gr0 = row0 + xr0, gr1 = row0 + xr1;
        xv0 = (gr0 < N) ? __ldcs((const float4*)&X[(long)gr0 * F + k0 + xk0]) : make_float4(0,0,0,0);
        xv1 = (gr1 < N) ? __ldcs((const float4*)&X[(long)gr1 * F + k0 + xk1]) : make_float4(0,0,0,0);
#pragma unroll
        for (int j = 0; j < 4; j++) {
            int kk = k0 + 2 * (wkp + j);
            wa[j] = W1[kk * F + wcc];
            wb[j] = W1[(kk + 1) * F + wcc];
        }
    };
    auto stage = [&](int b) {
        __half2* px0 = (__half2*)&Xs[b][xr0][xk0];
        px0[0] = __floats2half2_rn(xv0.x, xv0.y);
        px0[1] = __floats2half2_rn(xv0.z, xv0.w);
        __half2* px1 = (__half2*)&Xs[b][xr1][xk1];
        px1[0] = __floats2half2_rn(xv1.x, xv1.y);
        px1[1] = __floats2half2_rn(xv1.z, xv1.w);
#pragma unroll
        for (int j = 0; j < 4; j++) {
            __half2 h = __floats2half2_rn(wa[j], wb[j]);
            Ws[b][wkp + j][wcc] = *(uint32_t*)&h;
        }
    };

    fetch(0);
    stage(0);
    __syncthreads();

    int p = 0;
#pragma unroll
    for (int c = 0; c < 8; c++) {
        if (c < 7) fetch(c + 1);

        uint32_t bf[8][2];
#pragma unroll
        for (int nt = 0; nt < 8; nt++) {
            int cc = wc * 64 + nt * 8 + g;
            bf[nt][0] = Ws[p][tig][cc];
            bf[nt][1] = Ws[p][tig + 4][cc];
        }

#pragma unroll
        for (int rt = 0; rt < 2; rt++) {
            int rb = wr * 32 + rt * 16;
            uint32_t a0 = *(const uint32_t*)&Xs[p][rb + g][2 * tig];
            uint32_t a1 = *(const uint32_t*)&Xs[p][rb + g + 8][2 * tig];
            uint32_t a2 = *(const uint32_t*)&Xs[p][rb + g][2 * tig + 8];
            uint32_t a3 = *(const uint32_t*)&Xs[p][rb + g + 8][2 * tig + 8];
#pragma unroll
            for (int nt = 0; nt < 8; nt++) {
                float* d = acc[rt][nt];
                asm volatile(
                    "mma.sync.aligned.m16n8k16.row.col.f32.f16.f16.f32 "
                    "{%0,%1,%2,%3}, {%4,%5,%6,%7}, {%8,%9}, {%0,%1,%2,%3};"
                    : "+f"(d[0]), "+f"(d[1]), "+f"(d[2]), "+f"(d[3])
                    : "r"(a0), "r"(a1), "r"(a2), "r"(a3),
                      "r"(bf[nt][0]), "r"(bf[nt][1]));
            }
        }

        if (c < 7) {
            stage(1 - p);
            __syncthreads();
            p ^= 1;
        }
    }

#pragma unroll
    for (int rt = 0; rt < 2; rt++) {
        int r0g = row0 + wr * 32 + rt * 16 + g;
        int r1g = r0g + 8;
#pragma unroll
        for (int nt = 0; nt < 8; nt++) {
            int cc = wc * 64 + nt * 8 + 2 * tig;
            if (r0g < N)
                *(__half2*)&Y[(long)r0g * F + cc] = __floats2half2_rn(acc[rt][nt][0], acc[rt][nt][1]);
            if (r1g < N)
                *(__half2*)&Y[(long)r1g * F + cc] = __floats2half2_rn(acc[rt][nt][2], acc[rt][nt][3]);
        }
    }
}

// ---------------- layer 1 gather (CSR, fp16 messages) + fused h@W2 ----------
__device__ __forceinline__ void acc_row(float4& acc, const __half* base, int lane, float n) {
    uint2 u = ((const uint2*)base)[lane];
    float2 f01 = __half22float2(*reinterpret_cast<__half2*>(&u.x));
    float2 f23 = __half22float2(*reinterpret_cast<__half2*>(&u.y));
    acc.x += n * f01.x; acc.y += n * f01.y;
    acc.z += n * f23.x; acc.w += n * f23.y;
}

__global__ void k_gather1(const int* __restrict__ start, const unsigned int* __restrict__ edge,
                          const __half* __restrict__ xwh,
                          const float* __restrict__ dinv, const float* __restrict__ b1,
                          const float* __restrict__ W2,
                          float* __restrict__ emb, float* __restrict__ hw, int N) {
    int node = blockIdx.x * (blockDim.x >> 5) + (threadIdx.x >> 5);
    if (node >= N) return;
    int lane = threadIdx.x & 31;

    float dc = dinv[node];
    float4 acc = make_float4(0.f, 0.f, 0.f, 0.f);

    int e  = start[node];
    int e1 = start[node + 1];
    for (; e + 3 < e1; e += 4) {
        unsigned int p0 = edge[e],   p1 = edge[e+1], p2 = edge[e+2], p3 = edge[e+3];
        acc_row(acc, &xwh[(long)edge_row(p0) * F], lane, edge_w(p0));
        acc_row(acc, &xwh[(long)edge_row(p1) * F], lane, edge_w(p1));
        acc_row(acc, &xwh[(long)edge_row(p2) * F], lane, edge_w(p2));
        acc_row(acc, &xwh[(long)edge_row(p3) * F], lane, edge_w(p3));
    }
    for (; e < e1; e++) {
        unsigned int p0 = edge[e];
        acc_row(acc, &xwh[(long)edge_row(p0) * F], lane, edge_w(p0));
    }

    // self-loop (weight dinv_c), then scale whole sum by dinv_c
    acc_row(acc, &xwh[(long)node * F], lane, dc);
    acc.x *= dc; acc.y *= dc; acc.z *= dc; acc.w *= dc;

    float4 b = ((const float4*)b1)[lane];
    acc.x += b.x; acc.y += b.y; acc.z += b.z; acc.w += b.w;
    acc.x = (acc.x > 0.f) ? acc.x : expm1f(acc.x);
    acc.y = (acc.y > 0.f) ? acc.y : expm1f(acc.y);
    acc.z = (acc.z > 0.f) ? acc.z : expm1f(acc.z);
    acc.w = (acc.w > 0.f) ? acc.w : expm1f(acc.w);
    __stwt((float4*)&emb[(long)node * F + lane * 4], acc);

    float4 wv = ((const float4*)W2)[lane];
    float d = acc.x * wv.x + acc.y * wv.y + acc.z * wv.z + acc.w * wv.w;
#pragma unroll
    for (int o = 16; o > 0; o >>= 1) d += __shfl_xor_sync(0xFFFFFFFFu, d, o);
    if (lane == 0) hw[node] = d;
}

// ---------------- layer 2: thread per node, 4-edge unroll --------------------
__global__ void k_gather2(const int* __restrict__ start, const unsigned int* __restrict__ edge,
                          const float* __restrict__ hw,
                          const float* __restrict__ dinv, const float* __restrict__ b2,
                          float* __restrict__ out, int N) {
    int node = blockIdx.x * blockDim.x + threadIdx.x;
    if (node >= N) return;
    float dc = dinv[node];
    float sum = 0.0f;
    int e  = start[node];
    int e1 = start[node + 1];
    for (; e + 3 < e1; e += 4) {
        unsigned int p0 = edge[e],     p1 = edge[e + 1];
        unsigned int p2 = edge[e + 2], p3 = edge[e + 3];
        sum += edge_w(p0) * hw[edge_row(p0)] + edge_w(p1) * hw[edge_row(p1)]
             + edge_w(p2) * hw[edge_row(p2)] + edge_w(p3) * hw[edge_row(p3)];
    }
    for (; e < e1; e++) {
        unsigned int p0 = edge[e];
        sum += edge_w(p0) * hw[edge_row(p0)];
    }
    float v = dc * (sum + dc * hw[node]) + b2[0];
    out[node] = 1.0f / (1.0f + expf(-v));
}

// ---------------- launch ------------------------------------------------------
extern "C" void kernel_launch(void* const* d_in, const int* in_sizes, int n_in,
                              void* d_out, int out_size) {
    const float* x   = (const float*)d_in[0];
    const int*   ei  = (const int*)d_in[1];
    const float* ew  = (const float*)d_in[2];
    const float* W1  = (const float*)d_in[3];
    const float* b1  = (const float*)d_in[4];
    const float* W2  = (const float*)d_in[5];
    const float* b2  = (const float*)d_in[6];

    int N = in_sizes[0] / F;
    int E = in_sizes[2];
    const int* row = ei;
    const int* col = ei + E;

    float* out_pred = (float*)d_out;
    float* emb      = (float*)d_out + N;

    unsigned long long* packed = nullptr; cudaGetSymbolAddress((void**)&packed, g_packed);
    float*  dinv  = nullptr; cudaGetSymbolAddress((void**)&dinv,  g_dinv);
    __half* xwh   = nullptr; cudaGetSymbolAddress((void**)&xwh,   g_xwh);
    float*  hw    = nullptr; cudaGetSymbolAddress((void**)&hw,    g_hw);
    int*    start = nullptr; cudaGetSymbolAddress((void**)&start, g_start);
    int*    bsum  = nullptr; cudaGetSymbolAddress((void**)&bsum,  g_bsum);
    int*    rank  = nullptr; cudaGetSymbolAddress((void**)&rank,  g_rank);
    unsigned int* edge = nullptr; cudaGetSymbolAddress((void**)&edge, g_edge);

    int nb = (N + CHUNK - 1) / CHUNK;

    static cudaStream_t s2 = nullptr;
    static cudaEvent_t ev_fork = nullptr, ev_join = nullptr;
    if (s2 == nullptr) {
        cudaStreamCreateWithFlags(&s2, cudaStreamNonBlocking);
        cudaEventCreateWithFlags(&ev_fork, cudaEventDisableTiming);
        cudaEventCreateWithFlags(&ev_join, cudaEventDisableTiming);
    }

    cudaEventRecord(ev_fork, 0);
    cudaStreamWaitEvent(s2, ev_fork, 0);

    // main stream: fp16 tensor-core GEMM
    k_gemm_f16<<<(N + 127) / 128, 256>>>(x, W1, xwh, N);

    // s2: CSR build
    cudaMemsetAsync(packed, 0, (size_t)N * sizeof(unsigned long long), s2);
    k_edge_pass<<<(E + 255) / 256, 256, 0, s2>>>(col, ew, packed, rank, E);
    k_dinv_blocksum<<<nb, 256, 0, s2>>>(packed, dinv, bsum, N);
    k_scan_scatter<<<nb, 256, 0, s2>>>(packed, bsum, start, nb, N, E);
    k_permute<<<((E + 3) / 4 + 255) / 256, 256, 0, s2>>>(row, col, ew, dinv, start, rank, edge, E);

    cudaEventRecord(ev_join, s2);
    cudaStreamWaitEvent(0, ev_join, 0);

    k_gather1<<<(N + 7) / 8, 256>>>(start, edge, xwh, dinv, b1, W2, emb, hw, N);
    k_gather2<<<(N + 255) / 256, 256>>>(start, edge, hw, dinv, b2, out_pred, N);
}

// round 16
// speedup vs baseline: 1.2185x; 1.0854x over previous
#include <cuda_runtime.h>
#include <cuda_fp16.h>
#include <math.h>
#include <stdint.h>

#define MAX_N 100000
#define MAX_E 1600000
#define F 128
#define CHUNK 1024
#define NB ((MAX_N + CHUNK - 1) / CHUNK)
#define DEG_SCALE 33554432.0f    // 2^25 fixed-point for weighted degree

// ---------------- scratch (static device globals) ---------------------------
__device__ unsigned long long g_packed[MAX_N];      // hi: count, lo: deg fixed-point
__device__ float g_dinv[MAX_N];
__device__ __align__(16) __half g_xwh[MAX_N * F];   // dinv[r] * (x @ W1)[r], fp16
__device__ float g_hw[MAX_N];                       // dinv[r] * (h @ W2)[r]
__device__ int   g_start[MAX_N + 1];
__device__ int   g_bsum[NB + 1];
__device__ __align__(16) int g_rank[MAX_E];         // within-target rank of each edge
__device__ __align__(16) unsigned int g_edge[MAX_E]; // packed {r:17 | half(ew):15}, CSR-sorted

// ---------------- edge packing helpers ---------------------------------------
__device__ __forceinline__ unsigned int pack_edge(int r, float w) {
    unsigned short hb = __half_as_ushort(__float2half(w));
    return ((unsigned int)r << 15) | (hb & 0x7FFFu);
}
__device__ __forceinline__ int edge_row(unsigned int u) { return (int)(u >> 15); }
__device__ __forceinline__ float edge_w(unsigned int u) {
    return __half2float(__ushort_as_half((unsigned short)(u & 0x7FFFu)));
}

// ---------------- edge pass: ONE packed atomic per edge (thread-per-edge) ----
__global__ void k_edge_pass(const int* __restrict__ col, const float* __restrict__ ew,
                            unsigned long long* packed, int* __restrict__ rank, int E) {
    int e = blockIdx.x * blockDim.x + threadIdx.x;
    if (e < E) {
        int c = col[e];
        unsigned int q = __float2uint_rn(ew[e] * DEG_SCALE);
        unsigned long long old =
            atomicAdd(&packed[c], (1ULL << 32) | (unsigned long long)q);
        rank[e] = (int)(old >> 32);
    }
}

// fused: dinv (with +1 self-loop) + per-chunk block sums of counts
__global__ void k_dinv_blocksum(const unsigned long long* __restrict__ packed,
                                float* __restrict__ dinv, int* bsum, int N) {
    __shared__ int s[256];
    int base = blockIdx.x * CHUNK;
    int t = threadIdx.x;
    int local = 0;
#pragma unroll
    for (int j = 0; j < 4; j++) {
        int i = base + t * 4 + j;
        if (i < N) {
            unsigned long long p = packed[i];
            local += (int)(p >> 32);
            float d = 1.0f + (float)(unsigned int)(p & 0xFFFFFFFFu) * (1.0f / DEG_SCALE);
            dinv[i] = rsqrtf(d);
        }
    }
    s[t] = local;
    __syncthreads();
    for (int off = 128; off > 0; off >>= 1) {
        if (t < off) s[t] += s[t + off];
        __syncthreads();
    }
    if (t == 0) bsum[blockIdx.x] = s[0];
}

// scan_scatter with INLINE bsum prefix
__global__ void k_scan_scatter(const unsigned long long* __restrict__ packed,
                               const int* __restrict__ bsum, int* start,
                               int nb, int N, int E) {
    __shared__ int s[256];
    __shared__ int sb[128];
    int base = blockIdx.x * CHUNK;
    int t = threadIdx.x;

    if (t < 128) sb[t] = (t < nb) ? bsum[t] : 0;
    __syncthreads();
    for (int off = 1; off < 128; off <<= 1) {
        int x = 0;
        if (t < 128 && t >= off) x = sb[t - off];
        __syncthreads();
        if (t < 128) sb[t] += x;
        __syncthreads();
    }
    int block_prefix = (blockIdx.x > 0) ? sb[blockIdx.x - 1] : 0;

    int v[4];
    int local = 0;
#pragma unroll
    for (int j = 0; j < 4; j++) {
        int i = base + t * 4 + j;
        v[j] = (i < N) ? (int)(packed[i] >> 32) : 0;
        local += v[j];
    }
    s[t] = local;
    __syncthreads();
    for (int off = 1; off < 256; off <<= 1) {
        int x = (t >= off) ? s[t - off] : 0;
        __syncthreads();
        s[t] += x;
        __syncthreads();
    }
    int excl = ((t > 0) ? s[t - 1] : 0) + block_prefix;
#pragma unroll
    for (int j = 0; j < 4; j++) {
        int i = base + t * 4 + j;
        if (i < N) {
            start[i] = excl;
            excl += v[j];
        }
    }
    if (blockIdx.x == 0 && t == 0) start[N] = E;
}

// ---------------- permute: 4 edges/thread; store packed {r, half(ew)} --------
// NO dinv reads: dinv[r] is folded into the xws feature rows.
__global__ void k_permute(const int* __restrict__ row, const int* __restrict__ col,
                          const float* __restrict__ ew,
                          const int* __restrict__ start, const int* __restrict__ rank,
                          unsigned int* __restrict__ edge, int E) {
    int i = blockIdx.x * blockDim.x + threadIdx.x;
    int e = i * 4;
    if (e + 3 < E) {
        int4 r4 = *(const int4*)&row[e];
        int4 c4 = *(const int4*)&col[e];
        float4 w4 = *(const float4*)&ew[e];
        int4 k4 = *(const int4*)&rank[e];
        int pa = start[c4.x] + k4.x;
        int pb = start[c4.y] + k4.y;
        int pc = start[c4.z] + k4.z;
        int pd = start[c4.w] + k4.w;
        edge[pa] = pack_edge(r4.x, w4.x);
        edge[pb] = pack_edge(r4.y, w4.y);
        edge[pc] = pack_edge(r4.z, w4.z);
        edge[pd] = pack_edge(r4.w, w4.w);
    } else {
        for (; e < E; e++) {
            int pos = start[col[e]] + rank[e];
            edge[pos] = pack_edge(row[e], ew[e]);
        }
    }
}

// ---------------- fp16 tensor-core GEMM: Y(fp16) = dinv ⊙ (X @ W1) -----------
__global__ void __launch_bounds__(256, 2)
k_gemm_f16(const float* __restrict__ X, const float* __restrict__ W1,
           const float* __restrict__ dinv, __half* __restrict__ Y, int N) {
    __shared__ __half  Xs[2][128][24];
    __shared__ uint32_t Ws[2][8][136];

    int tid  = threadIdx.x;
    int lane = tid & 31;
    int wid  = tid >> 5;
    int wr   = wid >> 1;
    int wc   = wid & 1;
    int g    = lane >> 2;
    int tig  = lane & 3;
    int row0 = blockIdx.x * 128;

    int xr0 = tid >> 2,           xk0 = (tid & 3) * 4;
    int xr1 = (tid + 256) >> 2,   xk1 = (tid & 3) * 4;
    int wcc = tid & 127;
    int wkp = (tid >> 7) * 4;

    float acc[2][8][4];
#pragma unroll
    for (int rt = 0; rt < 2; rt++)
#pragma unroll
        for (int nt = 0; nt < 8; nt++)
#pragma unroll
            for (int j = 0; j < 4; j++) acc[rt][nt][j] = 0.0f;

    float4 xv0, xv1;
    float wa[4], wb[4];

    auto fetch = [&](int c) {
        int k0 = c * 16;
        int gr0 = row0 + xr0, gr1 = row0 + xr1;
        xv0 = (gr0 < N) ? __ldcs((const float4*)&X[(long)gr0 * F + k0 + xk0]) : make_float4(0,0,0,0);
        xv1 = (gr1 < N) ? __ldcs((const float4*)&X[(long)gr1 * F + k0 + xk1]) : make_float4(0,0,0,0);
#pragma unroll
        for (int j = 0; j < 4; j++) {
            int kk = k0 + 2 * (wkp + j);
            wa[j] = W1[kk * F + wcc];
            wb[j] = W1[(kk + 1) * F + wcc];
        }
    };
    auto stage = [&](int b) {
        __half2* px0 = (__half2*)&Xs[b][xr0][xk0];
        px0[0] = __floats2half2_rn(xv0.x, xv0.y);
        px0[1] = __floats2half2_rn(xv0.z, xv0.w);
        __half2* px1 = (__half2*)&Xs[b][xr1][xk1];
        px1[0] = __floats2half2_rn(xv1.x, xv1.y);
        px1[1] = __floats2half2_rn(xv1.z, xv1.w);
#pragma unroll
        for (int j = 0; j < 4; j++) {
            __half2 h = __floats2half2_rn(wa[j], wb[j]);
            Ws[b][wkp + j][wcc] = *(uint32_t*)&h;
        }
    };

    fetch(0);
    stage(0);
    __syncthreads();

    int p = 0;
#pragma unroll
    for (int c = 0; c < 8; c++) {
        if (c < 7) fetch(c + 1);

        uint32_t bf[8][2];
#pragma unroll
        for (int nt = 0; nt < 8; nt++) {
            int cc = wc * 64 + nt * 8 + g;
            bf[nt][0] = Ws[p][tig][cc];
            bf[nt][1] = Ws[p][tig + 4][cc];
        }

#pragma unroll
        for (int rt = 0; rt < 2; rt++) {
            int rb = wr * 32 + rt * 16;
            uint32_t a0 = *(const uint32_t*)&Xs[p][rb + g][2 * tig];
            uint32_t a1 = *(const uint32_t*)&Xs[p][rb + g + 8][2 * tig];
            uint32_t a2 = *(const uint32_t*)&Xs[p][rb + g][2 * tig + 8];
            uint32_t a3 = *(const uint32_t*)&Xs[p][rb + g + 8][2 * tig + 8];
#pragma unroll
            for (int nt = 0; nt < 8; nt++) {
                float* d = acc[rt][nt];
                asm volatile(
                    "mma.sync.aligned.m16n8k16.row.col.f32.f16.f16.f32 "
                    "{%0,%1,%2,%3}, {%4,%5,%6,%7}, {%8,%9}, {%0,%1,%2,%3};"
                    : "+f"(d[0]), "+f"(d[1]), "+f"(d[2]), "+f"(d[3])
                    : "r"(a0), "r"(a1), "r"(a2), "r"(a3),
                      "r"(bf[nt][0]), "r"(bf[nt][1]));
            }
        }

        if (c < 7) {
            stage(1 - p);
            __syncthreads();
            p ^= 1;
        }
    }

    // epilogue: scale rows by dinv[row], pack to half2
#pragma unroll
    for (int rt = 0; rt < 2; rt++) {
        int r0g = row0 + wr * 32 + rt * 16 + g;
        int r1g = r0g + 8;
        float d0 = (r0g < N) ? dinv[r0g] : 0.0f;
        float d1 = (r1g < N) ? dinv[r1g] : 0.0f;
#pragma unroll
        for (int nt = 0; nt < 8; nt++) {
            int cc = wc * 64 + nt * 8 + 2 * tig;
            if (r0g < N)
                *(__half2*)&Y[(long)r0g * F + cc] =
                    __floats2half2_rn(acc[rt][nt][0] * d0, acc[rt][nt][1] * d0);
            if (r1g < N)
                *(__half2*)&Y[(long)r1g * F + cc] =
                    __floats2half2_rn(acc[rt][nt][2] * d1, acc[rt][nt][3] * d1);
        }
    }
}

// ---------------- layer 1 gather (CSR, fp16 messages) + fused h@W2 ----------
__device__ __forceinline__ void acc_row(float4& acc, const __half* base, int lane, float n) {
    uint2 u = ((const uint2*)base)[lane];
    float2 f01 = __half22float2(*reinterpret_cast<__half2*>(&u.x));
    float2 f23 = __half22float2(*reinterpret_cast<__half2*>(&u.y));
    acc.x += n * f01.x; acc.y += n * f01.y;
    acc.z += n * f23.x; acc.w += n * f23.y;
}

__global__ void k_gather1(const int* __restrict__ start, const unsigned int* __restrict__ edge,
                          const __half* __restrict__ xwh,
                          const float* __restrict__ dinv, const float* __restrict__ b1,
                          const float* __restrict__ W2,
                          float* __restrict__ emb, float* __restrict__ hw, int N) {
    int node = blockIdx.x * (blockDim.x >> 5) + (threadIdx.x >> 5);
    if (node >= N) return;
    int lane = threadIdx.x & 31;

    float dc = dinv[node];
    float4 acc = make_float4(0.f, 0.f, 0.f, 0.f);

    int e  = start[node];
    int e1 = start[node + 1];
    for (; e + 3 < e1; e += 4) {
        unsigned int p0 = edge[e],   p1 = edge[e+1], p2 = edge[e+2], p3 = edge[e+3];
        acc_row(acc, &xwh[(long)edge_row(p0) * F], lane, edge_w(p0));
        acc_row(acc, &xwh[(long)edge_row(p1) * F], lane, edge_w(p1));
        acc_row(acc, &xwh[(long)edge_row(p2) * F], lane, edge_w(p2));
        acc_row(acc, &xwh[(long)edge_row(p3) * F], lane, edge_w(p3));
    }
    for (; e < e1; e++) {
        unsigned int p0 = edge[e];
        acc_row(acc, &xwh[(long)edge_row(p0) * F], lane, edge_w(p0));
    }

    // self-loop: xws[node] already carries dinv[node]; then scale sum by dinv_c
    acc_row(acc, &xwh[(long)node * F], lane, 1.0f);
    acc.x *= dc; acc.y *= dc; acc.z *= dc; acc.w *= dc;

    float4 b = ((const float4*)b1)[lane];
    acc.x += b.x; acc.y += b.y; acc.z += b.z; acc.w += b.w;
    acc.x = (acc.x > 0.f) ? acc.x : expm1f(acc.x);
    acc.y = (acc.y > 0.f) ? acc.y : expm1f(acc.y);
    acc.z = (acc.z > 0.f) ? acc.z : expm1f(acc.z);
    acc.w = (acc.w > 0.f) ? acc.w : expm1f(acc.w);
    __stwt((float4*)&emb[(long)node * F + lane * 4], acc);

    // hws[node] = dinv[node] * (h @ W2)
    float4 wv = ((const float4*)W2)[lane];
    float d = acc.x * wv.x + acc.y * wv.y + acc.z * wv.z + acc.w * wv.w;
#pragma unroll
    for (int o = 16; o > 0; o >>= 1) d += __shfl_xor_sync(0xFFFFFFFFu, d, o);
    if (lane == 0) hw[node] = dc * d;
}

// ---------------- layer 2: thread per node, 4-edge unroll --------------------
// hw[] holds dinv[r]*(h@W2)[r]; v = dc*(Σ ew*hws[r] + hws[node]) + b2
__global__ void k_gather2(const int* __restrict__ start, const unsigned int* __restrict__ edge,
                          const float* __restrict__ hw,
                          const float* __restrict__ dinv, const float* __restrict__ b2,
                          float* __restrict__ out, int N) {
    int node = blockIdx.x * blockDim.x + threadIdx.x;
    if (node >= N) return;
    float dc = dinv[node];
    float sum = 0.0f;
    int e  = start[node];
    int e1 = start[node + 1];
    for (; e + 3 < e1; e += 4) {
        unsigned int p0 = edge[e],     p1 = edge[e + 1];
        unsigned int p2 = edge[e + 2], p3 = edge[e + 3];
        sum += edge_w(p0) * hw[edge_row(p0)] + edge_w(p1) * hw[edge_row(p1)]
             + edge_w(p2) * hw[edge_row(p2)] + edge_w(p3) * hw[edge_row(p3)];
    }
    for (; e < e1; e++) {
        unsigned int p0 = edge[e];
        sum += edge_w(p0) * hw[edge_row(p0)];
    }
    float v = dc * (sum + hw[node]) + b2[0];
    out[node] = 1.0f / (1.0f + expf(-v));
}

// ---------------- launch ------------------------------------------------------
extern "C" void kernel_launch(void* const* d_in, const int* in_sizes, int n_in,
                              void* d_out, int out_size) {
    const float* x   = (const float*)d_in[0];
    const int*   ei  = (const int*)d_in[1];
    const float* ew  = (const float*)d_in[2];
    const float* W1  = (const float*)d_in[3];
    const float* b1  = (const float*)d_in[4];
    const float* W2  = (const float*)d_in[5];
    const float* b2  = (const float*)d_in[6];

    int N = in_sizes[0] / F;
    int E = in_sizes[2];
    const int* row = ei;
    const int* col = ei + E;

    float* out_pred = (float*)d_out;
    float* emb      = (float*)d_out + N;

    unsigned long long* packed = nullptr; cudaGetSymbolAddress((void**)&packed, g_packed);
    float*  dinv  = nullptr; cudaGetSymbolAddress((void**)&dinv,  g_dinv);
    __half* xwh   = nullptr; cudaGetSymbolAddress((void**)&xwh,   g_xwh);
    float*  hw    = nullptr; cudaGetSymbolAddress((void**)&hw,    g_hw);
    int*    start = nullptr; cudaGetSymbolAddress((void**)&start, g_start);
    int*    bsum  = nullptr; cudaGetSymbolAddress((void**)&bsum,  g_bsum);
    int*    rank  = nullptr; cudaGetSymbolAddress((void**)&rank,  g_rank);
    unsigned int* edge = nullptr; cudaGetSymbolAddress((void**)&edge, g_edge);

    int nb = (N + CHUNK - 1) / CHUNK;

    static cudaStream_t s2 = nullptr;
    static cudaEvent_t ev_fork = nullptr, ev_dinv = nullptr, ev_join = nullptr;
    if (s2 == nullptr) {
        cudaStreamCreateWithFlags(&s2, cudaStreamNonBlocking);
        cudaEventCreateWithFlags(&ev_fork, cudaEventDisableTiming);
        cudaEventCreateWithFlags(&ev_dinv, cudaEventDisableTiming);
        cudaEventCreateWithFlags(&ev_join, cudaEventDisableTiming);
    }

    cudaEventRecord(ev_fork, 0);
    cudaStreamWaitEvent(s2, ev_fork, 0);

    // s2: degree/histogram -> dinv, then CSR offsets + permute
    cudaMemsetAsync(packed, 0, (size_t)N * sizeof(unsigned long long), s2);
    k_edge_pass<<<(E + 255) / 256, 256, 0, s2>>>(col, ew, packed, rank, E);
    k_dinv_blocksum<<<nb, 256, 0, s2>>>(packed, dinv, bsum, N);
    cudaEventRecord(ev_dinv, s2);
    k_scan_scatter<<<nb, 256, 0, s2>>>(packed, bsum, start, nb, N, E);
    k_permute<<<((E + 3) / 4 + 255) / 256, 256, 0, s2>>>(row, col, ew, start, rank, edge, E);
    cudaEventRecord(ev_join, s2);

    // main: GEMM (needs dinv for fused row scaling), overlaps scan+permute
    cudaStreamWaitEvent(0, ev_dinv, 0);
    k_gemm_f16<<<(N + 127) / 128, 256>>>(x, W1, dinv, xwh, N);

    cudaStreamWaitEvent(0, ev_join, 0);
    k_gather1<<<(N + 7) / 8, 256>>>(start, edge, xwh, dinv, b1, W2, emb, hw, N);
    k_gather2<<<(N + 255) / 256, 256>>>(start, edge, hw, dinv, b2, out_pred, N);
}